// round 3
// baseline (speedup 1.0000x reference)
#include <cuda_runtime.h>
#include <cstdint>

// ---------------------------------------------------------------------------
// LSTM: B=256, T=784, F=1, H=256 (gates 4H=1024), then dense(1024)+relu, pred(10)
//
// Kernel 1 (persistent, clustered): 16 clusters x 8 CTAs, 256 threads/CTA.
//   - cluster c owns batches [16c, 16c+16)
//   - CTA rank r owns h-indices [32r, 32r+32) and gate columns
//     {g*256 + 32r .. +32 : g in i,j,f,o}  (128 cols -> Wh slice 256x128 f32 = 128KB smem)
//   - per step: gates = xproj + h @ Wh_slice (f32x2 FMA, 2 warps/SMSP keep the
//     fma pipe at its rt=2 floor), local c/h update (c in regs),
//     2KB h-slice pushed to all 8 cluster CTAs via st.shared::cluster with a
//     rank-rotated destination schedule (all-to-all permutation, no hot port),
//     one barrier.cluster per step. No grid-wide sync anywhere.
// Kernel 2: dense + relu + pred head from g_hlast scratch.
// ---------------------------------------------------------------------------

#define T_STEPS   784
#define BATCH     256
#define HDIM      256
#define NCLUST    16
#define CRANKS    8
#define BPC       16          // batches per cluster
#define THREADS1  256

// smem byte offsets (kernel 1, dynamic)
#define OFF_WH    0           // float2 [256][64]  = 131072 B
#define OFF_HBUF  131072      // float  [2][256][16] = 32768 B
#define OFF_GATES 163840      // float  [16][128] = 8192 B
#define SMEM1     172032

__device__ float g_hlast[BATCH * HDIM];

__device__ __forceinline__ unsigned long long pk2(float a, float b) {
    unsigned long long r;
    asm("mov.b64 %0,{%1,%2};" : "=l"(r) : "f"(a), "f"(b));
    return r;
}
__device__ __forceinline__ unsigned long long ffma2(unsigned long long a,
                                                    unsigned long long b,
                                                    unsigned long long c) {
    unsigned long long d;
    asm("fma.rn.f32x2 %0,%1,%2,%3;" : "=l"(d) : "l"(a), "l"(b), "l"(c));
    return d;
}
__device__ __forceinline__ void upk2(unsigned long long v, float& lo, float& hi) {
    asm("mov.b64 {%0,%1},%2;" : "=f"(lo), "=f"(hi) : "l"(v));
}
__device__ __forceinline__ float sigf(float x) {
    return __fdividef(1.f, 1.f + __expf(-x));
}
__device__ __forceinline__ float tanhf_(float x) {
    return fmaf(2.f, sigf(2.f * x), -1.f);   // tanh(x) = 2*sigmoid(2x) - 1
}

extern __shared__ char smem_raw[];

__global__ void __cluster_dims__(CRANKS, 1, 1) __launch_bounds__(THREADS1, 1)
lstm_kernel(const float* __restrict__ X,
            const float* __restrict__ Wl,     // (257, 1024): row0 = Wx, rows1.. = Wh
            const float* __restrict__ bl)     // (1024,)
{
    float2* Wh2  = reinterpret_cast<float2*>(smem_raw + OFF_WH);     // [k][cp]
    float*  hbuf = reinterpret_cast<float*>(smem_raw + OFF_HBUF);    // [2][256][16]
    float*  gates= reinterpret_cast<float*>(smem_raw + OFF_GATES);   // [b][128]

    const int tid = threadIdx.x;
    const int cl  = blockIdx.x >> 3;
    uint32_t r;
    asm("mov.u32 %0, %%cluster_ctarank;" : "=r"(r));
    const int b0g = cl * BPC;

    // ---- load Wh slice into smem as (col,col+1) float2 pairs --------------
    for (int i = tid; i < 256 * 64; i += THREADS1) {
        int k = i >> 6, cpx = i & 63;
        int gcol = ((cpx >> 4) << 8) + (int)r * 32 + ((cpx & 15) << 1);
        const float* src = Wl + (1 + k) * 1024 + gcol;
        Wh2[k * 64 + cpx] = make_float2(src[0], src[1]);
    }
    // zero both h buffers
    for (int i = tid; i < 2 * 256 * 16; i += THREADS1) hbuf[i] = 0.f;

    const int cp = tid & 63;   // colpair 0..63 (local cols 2cp, 2cp+1)
    const int bq = tid >> 6;   // batch quad 0..3 (GEMM role: batches bq*4..+3)
    const int kl = tid & 31;   // update role: local h index
    const int bp2 = tid >> 5;  // update role: batch pair 0..7 (batches bp2*2..+1)

    // per-thread constants for xproj: global cols of this thread's pair
    const int gc0 = ((cp >> 4) << 8) + (int)r * 32 + ((cp & 15) << 1);
    const unsigned long long wxd0 = pk2(Wl[gc0],     Wl[gc0]);
    const unsigned long long wxd1 = pk2(Wl[gc0 + 1], Wl[gc0 + 1]);
    const unsigned long long bld0 = pk2(bl[gc0],     bl[gc0]);
    const unsigned long long bld1 = pk2(bl[gc0 + 1], bl[gc0 + 1]);

    // peer h-buffer base addresses (shared::cluster), in rotated push order:
    // rank r pushes to r+1, r+2, ..., r+7, then itself — at every phase of the
    // all-to-all burst the 8 producers hit 8 distinct consumer smem ports.
    uint32_t hb_sa = (uint32_t)__cvta_generic_to_shared(hbuf);
    uint32_t pb[CRANKS];
#pragma unroll
    for (int i = 0; i < CRANKS; i++) {
        uint32_t dst = ((uint32_t)r + 1u + (uint32_t)i) & 7u;
        asm("mapa.shared::cluster.u32 %0, %1, %2;" : "=r"(pb[i]) : "r"(hb_sa), "r"(dst));
    }

    float creg[2] = {0.f, 0.f};

    // x for step 0 (GEMM-role batches bq*4..+3)
    float xc[4];
#pragma unroll
    for (int j = 0; j < 4; j++)
        xc[j] = __ldg(X + (b0g + bq * 4 + j) * T_STEPS + 0);

    __syncthreads();
    asm volatile("barrier.cluster.arrive.aligned;\n\t"
                 "barrier.cluster.wait.aligned;" ::: "memory");

    for (int t = 0; t < T_STEPS; t++) {
        const int rbuf = t & 1;

        // ---- init acc with xproj + bias: acc = x*Wx + b ------------------
        unsigned long long xp0 = pk2(xc[0], xc[1]);
        unsigned long long xp1 = pk2(xc[2], xc[3]);
        unsigned long long a00 = ffma2(xp0, wxd0, bld0);
        unsigned long long a01 = ffma2(xp1, wxd0, bld0);
        unsigned long long a10 = ffma2(xp0, wxd1, bld1);
        unsigned long long a11 = ffma2(xp1, wxd1, bld1);

        // prefetch next-step x (latency hidden behind the GEMM)
        const int tn = (t + 1 < T_STEPS) ? (t + 1) : t;
#pragma unroll
        for (int j = 0; j < 4; j++)
            xc[j] = __ldg(X + (b0g + bq * 4 + j) * T_STEPS + tn);

        // ---- GEMM: gates += h(t) @ Wh_slice ------------------------------
        // Per k per thread: 1 LDS.64 + 1 broadcast LDS.128 + 2 MOV + 4 FFMA2.
        const float2* wp = Wh2 + cp;
        const ulonglong2* hp =
            reinterpret_cast<const ulonglong2*>(hbuf + rbuf * 4096) + bq;
#pragma unroll 4
        for (int k = 0; k < 256; k++) {
            float2 w = wp[k * 64];                 // Wh[k][2cp], Wh[k][2cp+1]
            ulonglong2 h4 = hp[k * 4];             // h[k][bq*4 .. +3] as 2 f32x2
            unsigned long long w0 = pk2(w.x, w.x);
            unsigned long long w1 = pk2(w.y, w.y);
            a00 = ffma2(w0, h4.x, a00);
            a01 = ffma2(w0, h4.y, a01);
            a10 = ffma2(w1, h4.x, a10);
            a11 = ffma2(w1, h4.y, a11);
        }

        // ---- scatter gates to smem [b][col] ------------------------------
        {
            float lo, hi;
            const int c0 = 2 * cp, bb = bq * 4;
            upk2(a00, lo, hi); gates[(bb+0)*128 + c0]   = lo; gates[(bb+1)*128 + c0]   = hi;
            upk2(a01, lo, hi); gates[(bb+2)*128 + c0]   = lo; gates[(bb+3)*128 + c0]   = hi;
            upk2(a10, lo, hi); gates[(bb+0)*128 + c0+1] = lo; gates[(bb+1)*128 + c0+1] = hi;
            upk2(a11, lo, hi); gates[(bb+2)*128 + c0+1] = lo; gates[(bb+3)*128 + c0+1] = hi;
        }
        __syncthreads();

        // ---- c/h update for this CTA's h-slice (c lives in registers) ----
        float hv[2];
#pragma unroll
        for (int j = 0; j < 2; j++) {
            const int b = bp2 * 2 + j;
            const float* gb = gates + b * 128 + kl;
            float gi = gb[0], gj = gb[32], gf = gb[64], go = gb[96];
            float cc = sigf(gf + 1.f) * creg[j] + sigf(gi) * tanhf_(gj);
            creg[j] = cc;
            hv[j] = sigf(go) * tanhf_(cc);
        }

        // ---- push new h slice to all 8 cluster CTAs (rotated order) ------
        const uint32_t off =
            (uint32_t)((((rbuf ^ 1) * 4096) + ((int)r * 32 + kl) * 16 + bp2 * 2) * 4);
#pragma unroll
        for (int i = 0; i < CRANKS; i++) {
            asm volatile("st.shared::cluster.v2.f32 [%0], {%1,%2};"
                         :: "r"(pb[i] + off), "f"(hv[0]), "f"(hv[1])
                         : "memory");
        }
        asm volatile("barrier.cluster.arrive.aligned;\n\t"
                     "barrier.cluster.wait.aligned;" ::: "memory");
    }

    // ---- write h_last (parity: T=784 even -> final h lands in buffer 0) --
    if (r == 0) {
        for (int i = tid; i < BPC * HDIM; i += THREADS1) {
            int b = i >> 8, k = i & 255;
            g_hlast[(b0g + b) * HDIM + k] = hbuf[k * 16 + b];
        }
    }
}

// ---------------------------------------------------------------------------
// Kernel 2: dense = relu(h_last @ W_dense + b_dense); logits = dense @ W_pred + b_pred
// 32 blocks x 8 batches, 256 threads.
// ---------------------------------------------------------------------------
__global__ void __launch_bounds__(256)
head_kernel(const float* __restrict__ Wd, const float* __restrict__ bd,
            const float* __restrict__ Wp, const float* __restrict__ bp,
            float* __restrict__ out)
{
    __shared__ float h8[8][256];
    __shared__ float d8[8][1024];
    const int tid = threadIdx.x;
    const int b0 = blockIdx.x * 8;

    for (int i = tid; i < 8 * 256; i += 256)
        h8[i >> 8][i & 255] = g_hlast[(b0 + (i >> 8)) * 256 + (i & 255)];
    __syncthreads();

    float acc[4][8];
#pragma unroll
    for (int j = 0; j < 4; j++)
#pragma unroll
        for (int b = 0; b < 8; b++) acc[j][b] = 0.f;

    for (int k = 0; k < 256; k++) {
        float w0 = Wd[k * 1024 + tid];
        float w1 = Wd[k * 1024 + tid + 256];
        float w2 = Wd[k * 1024 + tid + 512];
        float w3 = Wd[k * 1024 + tid + 768];
#pragma unroll
        for (int b = 0; b < 8; b++) {
            float hv = h8[b][k];
            acc[0][b] = fmaf(w0, hv, acc[0][b]);
            acc[1][b] = fmaf(w1, hv, acc[1][b]);
            acc[2][b] = fmaf(w2, hv, acc[2][b]);
            acc[3][b] = fmaf(w3, hv, acc[3][b]);
        }
    }
#pragma unroll
    for (int j = 0; j < 4; j++) {
        const int d = tid + j * 256;
        const float bv = bd[d];
#pragma unroll
        for (int b = 0; b < 8; b++)
            d8[b][d] = fmaxf(acc[j][b] + bv, 0.f);
    }
    __syncthreads();

    if (tid < 80) {
        const int b = tid / 10, c = tid % 10;
        float a = bp[c];
        for (int d = 0; d < 1024; d++)
            a = fmaf(d8[b][d], Wp[d * 10 + c], a);
        out[(b0 + b) * 10 + c] = a;
    }
}

// ---------------------------------------------------------------------------
extern "C" void kernel_launch(void* const* d_in, const int* in_sizes, int n_in,
                              void* d_out, int out_size) {
    const float* X  = (const float*)d_in[0];
    const float* Wl = (const float*)d_in[1];
    const float* bl = (const float*)d_in[2];
    const float* Wd = (const float*)d_in[3];
    const float* bd = (const float*)d_in[4];
    const float* Wp = (const float*)d_in[5];
    const float* bp = (const float*)d_in[6];
    float* out = (float*)d_out;

    cudaFuncSetAttribute(lstm_kernel,
                         cudaFuncAttributeMaxDynamicSharedMemorySize, SMEM1);
    lstm_kernel<<<NCLUST * CRANKS, THREADS1, SMEM1>>>(X, Wl, bl);
    head_kernel<<<32, 256>>>(Wd, bd, Wp, bp, out);
}